// round 2
// baseline (speedup 1.0000x reference)
#include <cuda_runtime.h>
#include <math.h>

// Problem dims
#define HH 160
#define WW 192
#define DD 160
#define WD (WW*DD)          // 30720
#define NV (HH*WW*DD)       // 4915200
#define NV3 (3*NV)          // 14745600
#define PAD 4
#define WINSZ 9
#define NWIN 729.0f

#define RED_BLOCKS 1024

// Scratch (device globals; allocation-free per harness rules)
__device__ float g_flowA[NV3];
__device__ float g_flowB[NV3];
__device__ float g_m[NV3];
__device__ float g_v[NV3];
__device__ float g_vh[NV3];
__device__ float g_t0[NV3];   // 3-field ping
__device__ float g_t1[NV3];   // 3-field pong
__device__ float g_I[NV];     // warped image
__device__ float g_Jsum[NV];
__device__ float g_J2sum[NV];
__device__ float g_gI[NV];
__device__ double g_part[RED_BLOCKS];

// ---------------------------------------------------------------------------
__global__ void k_init(const float* __restrict__ f0) {
    int i = blockIdx.x * blockDim.x + threadIdx.x;
    if (i < NV3) {
        g_flowA[i] = f0[i];
        g_m[i] = 0.f; g_v[i] = 0.f; g_vh[i] = 0.f;
    }
}

// ---------------------------------------------------------------------------
__device__ __forceinline__ float fetchx(const float* __restrict__ x, int h, int w, int d) {
    if ((unsigned)h < HH && (unsigned)w < WW && (unsigned)d < DD)
        return __ldg(&x[(h * WW + w) * DD + d]);
    return 0.f;
}

// Warp forward: I = trilinear sample of x at (grid + flow), zero outside.
// parity: 0 -> read flowA, 1 -> read flowB
__global__ void k_warp(const float* __restrict__ x, int parity) {
    int idx = blockIdx.x * blockDim.x + threadIdx.x;
    if (idx >= NV) return;
    const float* __restrict__ flow = parity ? g_flowB : g_flowA;
    int h = idx / WD;
    int r = idx - h * WD;
    int w = r / DD;
    int d = r - w * DD;

    float ch = (float)h + flow[idx];
    float cw = (float)w + flow[NV + idx];
    float cd = (float)d + flow[2 * NV + idx];

    float fh = floorf(ch), fw = floorf(cw), fd = floorf(cd);
    int i0 = (int)fh, j0 = (int)fw, k0 = (int)fd;
    float ah = ch - fh, aw = cw - fw, ad = cd - fd;

    float v000 = fetchx(x, i0,     j0,     k0);
    float v001 = fetchx(x, i0,     j0,     k0 + 1);
    float v010 = fetchx(x, i0,     j0 + 1, k0);
    float v011 = fetchx(x, i0,     j0 + 1, k0 + 1);
    float v100 = fetchx(x, i0 + 1, j0,     k0);
    float v101 = fetchx(x, i0 + 1, j0,     k0 + 1);
    float v110 = fetchx(x, i0 + 1, j0 + 1, k0);
    float v111 = fetchx(x, i0 + 1, j0 + 1, k0 + 1);

    float wh0 = 1.f - ah, wh1 = ah;
    float ww0 = 1.f - aw, ww1 = aw;
    float wd0 = 1.f - ad, wd1 = ad;

    float val = v000 * (wh0 * ww0 * wd0) + v001 * (wh0 * ww0 * wd1)
              + v010 * (wh0 * ww1 * wd0) + v011 * (wh0 * ww1 * wd1)
              + v100 * (wh1 * ww0 * wd0) + v101 * (wh1 * ww0 * wd1)
              + v110 * (wh1 * ww1 * wd0) + v111 * (wh1 * ww1 * wd1);
    g_I[idx] = val;
}

// ---------------------------------------------------------------------------
// D-axis (contiguous) conv passes. One block per (h,w) row, 160 threads.

// Forward: fields (I, I*I, I*J) from I and y, on the fly.
__global__ void k_convD_f(const float* __restrict__ y) {
    int row = blockIdx.x;      // 0..HH*WW-1
    int d = threadIdx.x;       // 0..DD-1
    __shared__ float sI[DD + 2 * PAD];
    __shared__ float sJ[DD + 2 * PAD];
    int base = row * DD;
    sI[d + PAD] = g_I[base + d];
    sJ[d + PAD] = y[base + d];
    if (d < PAD) {
        sI[d] = 0.f; sJ[d] = 0.f;
        sI[DD + PAD + d] = 0.f; sJ[DD + PAD + d] = 0.f;
    }
    __syncthreads();
    float a = 0.f, b = 0.f, c = 0.f;
#pragma unroll
    for (int j = 0; j < WINSZ; j++) {
        float iv = sI[d + j], jv = sJ[d + j];
        a += iv; b += iv * iv; c += iv * jv;
    }
    g_t0[base + d] = a;
    g_t0[NV + base + d] = b;
    g_t0[2 * NV + base + d] = c;
}

// Generic 3-field D conv: t0 -> t1
__global__ void k_convD_3() {
    int row = blockIdx.x;
    int d = threadIdx.x;
    __shared__ float s0[DD + 2 * PAD];
    __shared__ float s1[DD + 2 * PAD];
    __shared__ float s2[DD + 2 * PAD];
    int base = row * DD;
    s0[d + PAD] = g_t0[base + d];
    s1[d + PAD] = g_t0[NV + base + d];
    s2[d + PAD] = g_t0[2 * NV + base + d];
    if (d < PAD) {
        s0[d] = s1[d] = s2[d] = 0.f;
        s0[DD + PAD + d] = s1[DD + PAD + d] = s2[DD + PAD + d] = 0.f;
    }
    __syncthreads();
    float a = 0.f, b = 0.f, c = 0.f;
#pragma unroll
    for (int j = 0; j < WINSZ; j++) { a += s0[d + j]; b += s1[d + j]; c += s2[d + j]; }
    g_t1[base + d] = a;
    g_t1[NV + base + d] = b;
    g_t1[2 * NV + base + d] = c;
}

// J-precompute D pass: fields (J, J*J) -> t0 fields 0,1
__global__ void k_convD_J(const float* __restrict__ y) {
    int row = blockIdx.x;
    int d = threadIdx.x;
    __shared__ float sJ[DD + 2 * PAD];
    int base = row * DD;
    sJ[d + PAD] = y[base + d];
    if (d < PAD) { sJ[d] = 0.f; sJ[DD + PAD + d] = 0.f; }
    __syncthreads();
    float a = 0.f, b = 0.f;
#pragma unroll
    for (int j = 0; j < WINSZ; j++) { float jv = sJ[d + j]; a += jv; b += jv * jv; }
    g_t0[base + d] = a;
    g_t0[NV + base + d] = b;
}

// ---------------------------------------------------------------------------
// W-axis conv (stride DD). dir=0: t0->t1, dir=1: t1->t0. 3 fields.
__global__ void k_conv3_W(int dir) {
    int idx = blockIdx.x * blockDim.x + threadIdx.x;
    if (idx >= NV) return;
    const float* __restrict__ src = dir ? g_t1 : g_t0;
    float* __restrict__ dst = dir ? g_t0 : g_t1;
    int w = (idx / DD) % WW;
    float a = 0.f, b = 0.f, c = 0.f;
#pragma unroll
    for (int j = -PAD; j <= PAD; j++) {
        int wq = w + j;
        if ((unsigned)wq < WW) {
            int q = idx + j * DD;
            a += src[q]; b += src[NV + q]; c += src[2 * NV + q];
        }
    }
    dst[idx] = a; dst[NV + idx] = b; dst[2 * NV + idx] = c;
}

// 2-field W conv for J precompute: t0 -> t1
__global__ void k_conv2_W() {
    int idx = blockIdx.x * blockDim.x + threadIdx.x;
    if (idx >= NV) return;
    int w = (idx / DD) % WW;
    float a = 0.f, b = 0.f;
#pragma unroll
    for (int j = -PAD; j <= PAD; j++) {
        int wq = w + j;
        if ((unsigned)wq < WW) {
            int q = idx + j * DD;
            a += g_t0[q]; b += g_t0[NV + q];
        }
    }
    g_t1[idx] = a; g_t1[NV + idx] = b;
}

// 2-field H conv for J precompute: t1 -> (Jsum, J2sum)
__global__ void k_conv2_H() {
    int idx = blockIdx.x * blockDim.x + threadIdx.x;
    if (idx >= NV) return;
    int h = idx / WD;
    float a = 0.f, b = 0.f;
#pragma unroll
    for (int j = -PAD; j <= PAD; j++) {
        int hq = h + j;
        if ((unsigned)hq < HH) {
            int q = idx + j * WD;
            a += g_t1[q]; b += g_t1[NV + q];
        }
    }
    g_Jsum[idx] = a; g_J2sum[idx] = b;
}

// ---------------------------------------------------------------------------
// H conv (forward) fused with NCC adjoint coefficients. Reads t1, writes t0.
__global__ void k_convH_coeff() {
    int idx = blockIdx.x * blockDim.x + threadIdx.x;
    if (idx >= NV) return;
    int h = idx / WD;
    float A = 0.f, C = 0.f, E = 0.f;
#pragma unroll
    for (int j = -PAD; j <= PAD; j++) {
        int hq = h + j;
        if ((unsigned)hq < HH) {
            int q = idx + j * WD;
            A += g_t1[q]; C += g_t1[NV + q]; E += g_t1[2 * NV + q];
        }
    }
    float B  = g_Jsum[idx];
    float Dv = g_J2sum[idx];
    float uI = A * (1.f / NWIN);
    float uJ = B * (1.f / NWIN);
    float cross = E - uJ * A - uI * B + uI * uJ * NWIN;
    float Ivar  = C - 2.f * uI * A + uI * uI * NWIN;
    float Jvar  = Dv - 2.f * uJ * B + uJ * uJ * NWIN;
    float denom = Ivar * Jvar + 1e-5f;
    float r = cross / denom;
    const float s = -1.f / (float)NV;   // d(-mean)/dcc
    float gE = s * 2.f * r;
    float gC = -s * (r * r) * Jvar;
    float gA = s * (-2.f * r * uJ + 2.f * (r * r) * Jvar * uI);
    g_t0[idx] = gA;
    g_t0[NV + idx] = gC;
    g_t0[2 * NV + idx] = gE;
}

// H conv (backward) fused with gI assembly. Reads t0, writes g_gI.
__global__ void k_convH_gI(const float* __restrict__ y) {
    int idx = blockIdx.x * blockDim.x + threadIdx.x;
    if (idx >= NV) return;
    int h = idx / WD;
    float wa = 0.f, wc = 0.f, we = 0.f;
#pragma unroll
    for (int j = -PAD; j <= PAD; j++) {
        int hq = h + j;
        if ((unsigned)hq < HH) {
            int q = idx + j * WD;
            wa += g_t0[q]; wc += g_t0[NV + q]; we += g_t0[2 * NV + q];
        }
    }
    g_gI[idx] = wa + 2.f * g_I[idx] * wc + y[idx] * we;
}

// ---------------------------------------------------------------------------
// Fused gradient + Adam(amsgrad): reads flow_cur (incl. neighbors), writes flow_nxt.
// parity: 0 -> cur=A, nxt=B ; 1 -> cur=B, nxt=A
__global__ void k_grad_adam(const float* __restrict__ x, int parity,
                            float bc1, float sbc2) {
    int idx = blockIdx.x * blockDim.x + threadIdx.x;
    if (idx >= NV) return;
    const float* __restrict__ cur = parity ? g_flowB : g_flowA;
    float* __restrict__ nxt = parity ? g_flowA : g_flowB;

    int h = idx / WD;
    int r = idx - h * WD;
    int w = r / DD;
    int d = r - w * DD;

    float fH = cur[idx];
    float fW = cur[NV + idx];
    float fD = cur[2 * NV + idx];

    float ch = (float)h + fH;
    float cw = (float)w + fW;
    float cd = (float)d + fD;
    float fh = floorf(ch), fw = floorf(cw), fd = floorf(cd);
    int i0 = (int)fh, j0 = (int)fw, k0 = (int)fd;
    float ah = ch - fh, aw = cw - fw, ad = cd - fd;

    float v000 = fetchx(x, i0,     j0,     k0);
    float v001 = fetchx(x, i0,     j0,     k0 + 1);
    float v010 = fetchx(x, i0,     j0 + 1, k0);
    float v011 = fetchx(x, i0,     j0 + 1, k0 + 1);
    float v100 = fetchx(x, i0 + 1, j0,     k0);
    float v101 = fetchx(x, i0 + 1, j0,     k0 + 1);
    float v110 = fetchx(x, i0 + 1, j0 + 1, k0);
    float v111 = fetchx(x, i0 + 1, j0 + 1, k0 + 1);

    float wh0 = 1.f - ah, wh1 = ah;
    float ww0 = 1.f - aw, ww1 = aw;
    float wd0 = 1.f - ad, wd1 = ad;

    // d(interp)/d(coord) per axis (corner values outside are constant 0)
    float dch = ww0 * wd0 * (v100 - v000) + ww0 * wd1 * (v101 - v001)
              + ww1 * wd0 * (v110 - v010) + ww1 * wd1 * (v111 - v011);
    float dcw = wh0 * wd0 * (v010 - v000) + wh0 * wd1 * (v011 - v001)
              + wh1 * wd0 * (v110 - v100) + wh1 * wd1 * (v111 - v101);
    float dcd = wh0 * ww0 * (v001 - v000) + wh0 * ww1 * (v011 - v010)
              + wh1 * ww0 * (v101 - v100) + wh1 * ww1 * (v111 - v110);

    float gi = g_gI[idx];

    // grad3d_l2 backward: per-axis counts over flow [1,3,H,W,D]
    const float coefH = 2.f / (3.f * (float)(3 * (HH - 1) * WW * DD));
    const float coefW = 2.f / (3.f * (float)(3 * HH * (WW - 1) * DD));
    const float coefD = 2.f / (3.f * (float)(3 * HH * WW * (DD - 1)));

    float dint[3] = { dch, dcw, dcd };
#pragma unroll
    for (int c = 0; c < 3; c++) {
        int off = c * NV + idx;
        float fc = (c == 0) ? fH : (c == 1) ? fW : fD;
        float tH = 0.f, tW = 0.f, tD = 0.f;
        if (h > 0)      tH += fc - cur[off - WD];
        if (h < HH - 1) tH -= cur[off + WD] - fc;
        if (w > 0)      tW += fc - cur[off - DD];
        if (w < WW - 1) tW -= cur[off + DD] - fc;
        if (d > 0)      tD += fc - cur[off - 1];
        if (d < DD - 1) tD -= cur[off + 1] - fc;
        float g = gi * dint[c] + coefH * tH + coefW * tW + coefD * tD;

        // Adam(amsgrad) pointwise
        float m = 0.9f * g_m[off] + 0.1f * g;
        float v = 0.999f * g_v[off] + 0.001f * g * g;
        float vh = fmaxf(g_vh[off], v);
        g_m[off] = m; g_v[off] = v; g_vh[off] = vh;
        float m_hat = m / bc1;
        float denom = sqrtf(vh) / sbc2 + 1e-8f;
        nxt[off] = fc - 0.1f * m_hat / denom;
    }
}

// ---------------------------------------------------------------------------
// Final MSE: deterministic two-stage reduction (double accumulation).
// parity of the FINAL flow buffer: 5 iters -> final in B (parity arg = 1).
__global__ void k_mse_part(const float* __restrict__ f0, int finalB) {
    const float* __restrict__ flow = finalB ? g_flowB : g_flowA;
    __shared__ double sd[256];
    double acc = 0.0;
    for (int i = blockIdx.x * blockDim.x + threadIdx.x; i < NV3;
         i += gridDim.x * blockDim.x) {
        float dlt = flow[i] - f0[i];
        acc += (double)dlt * (double)dlt;
    }
    sd[threadIdx.x] = acc;
    __syncthreads();
    for (int st = 128; st > 0; st >>= 1) {
        if (threadIdx.x < st) sd[threadIdx.x] += sd[threadIdx.x + st];
        __syncthreads();
    }
    if (threadIdx.x == 0) g_part[blockIdx.x] = sd[0];
}

__global__ void k_mse_final(float* __restrict__ out) {
    __shared__ double sd[256];
    double acc = 0.0;
    for (int i = threadIdx.x; i < RED_BLOCKS; i += 256) acc += g_part[i];
    sd[threadIdx.x] = acc;
    __syncthreads();
    for (int st = 128; st > 0; st >>= 1) {
        if (threadIdx.x < st) sd[threadIdx.x] += sd[threadIdx.x + st];
        __syncthreads();
    }
    if (threadIdx.x == 0) out[0] = (float)(sd[0] / (double)NV3);
}

// ---------------------------------------------------------------------------
extern "C" void kernel_launch(void* const* d_in, const int* in_sizes, int n_in,
                              void* d_out, int out_size) {
    const float* x  = (const float*)d_in[0];
    const float* y  = (const float*)d_in[1];
    const float* f0 = (const float*)d_in[2];
    float* out = (float*)d_out;
    (void)in_sizes; (void)n_in; (void)out_size;

    const int NB  = (NV  + 255) / 256;   // 19200
    const int NB3 = (NV3 + 255) / 256;   // 57600

    k_init<<<NB3, 256>>>(f0);

    // Precompute J window sums (constant across Adam steps)
    k_convD_J<<<HH * WW, DD>>>(y);
    k_conv2_W<<<NB, 256>>>();
    k_conv2_H<<<NB, 256>>>();

    for (int t = 1; t <= 5; t++) {
        int parity = (t - 1) & 1;             // which buffer holds current flow
        k_warp<<<NB, 256>>>(x, parity);
        k_convD_f<<<HH * WW, DD>>>(y);
        k_conv3_W<<<NB, 256>>>(0);            // t0 -> t1
        k_convH_coeff<<<NB, 256>>>();         // t1 -> t0 (gA,gC,gE)
        k_convD_3<<<HH * WW, DD>>>();         // t0 -> t1
        k_conv3_W<<<NB, 256>>>(1);            // t1 -> t0
        k_convH_gI<<<NB, 256>>>(y);           // t0 -> gI
        double bc1 = 1.0 - pow(0.9, (double)t);
        double bc2 = 1.0 - pow(0.999, (double)t);
        k_grad_adam<<<NB, 256>>>(x, parity, (float)bc1, (float)sqrt(bc2));
    }

    k_mse_part<<<RED_BLOCKS, 256>>>(f0, 1);   // after 5 iters final flow is in B
    k_mse_final<<<1, 256>>>(out);
}